// round 3
// baseline (speedup 1.0000x reference)
#include <cuda_runtime.h>
#include <math.h>

#define BB   1024
#define TT   512
#define HH   64
#define KK   128
#define ROWS 8
#define NTHR 256
#define VPITCH 132          // words per input row in smem (conflict-free padding)
#define LOG2E 1.4426950408889634f

// Scratch (static __device__ arrays are the allowed scratch mechanism)
__device__ float g_h1[(size_t)BB * TT * HH];   // layer-0 hidden sequence [B][T][H]
__device__ float g_hlast[BB * HH];             // layer-1 final hidden state

__device__ __forceinline__ void fma2(unsigned long long &d,
                                     unsigned long long a, unsigned long long b) {
    asm("fma.rn.f32x2 %0, %1, %2, %0;" : "+l"(d) : "l"(a), "l"(b));
}
__device__ __forceinline__ float ex2f(float x) {
    float r; asm("ex2.approx.f32 %0, %1;" : "=f"(r) : "f"(x)); return r;
}
__device__ __forceinline__ float rcpf(float x) {
    float r; asm("rcp.approx.f32 %0, %1;" : "=f"(r) : "f"(x)); return r;
}
__device__ __forceinline__ float2 unpack2(unsigned long long v) {
    float2 f; asm("mov.b64 {%0, %1}, %2;" : "=f"(f.x), "=f"(f.y) : "l"(v)); return f;
}
__device__ __forceinline__ float fsig(float x) {      // sigmoid, ~1e-7 rel err
    return rcpf(1.0f + ex2f(-LOG2E * x));
}
__device__ __forceinline__ float ftanhf(float x) {    // tanh = 2*sig(2x)-1
    return fmaf(rcpf(1.0f + ex2f(-2.0f * LOG2E * x)), 2.0f, -1.0f);
}

// One LSTM layer, batch-first, PyTorch gate order (i,f,g,o).
// CTA = 8 batch rows, 256 threads = (unit j 0..63) x (row-group rg 0..3).
// Thread (j, rg) computes ALL FOUR gates of unit j for rows {2rg, 2rg+1},
// so the c/h update is fully thread-local (no shuffles, no exchange).
// Per 4-k chunk: 2 v-LDS.128 + 4 w-LDS.128 feed 16 FFMA2 (fp32x2 packed
// over k-parity). Weights are read from SMEM exactly once per CTA per step.
__global__ void __launch_bounds__(NTHR, 1)
lstm_layer(const float* __restrict__ x_in,
           const float* __restrict__ w_ih, const float* __restrict__ w_hh,
           const float* __restrict__ b_ih, const float* __restrict__ b_hh,
           int store_seq, int store_last, int x_is_scratch)
{
    extern __shared__ float sm[];
    float* wq = sm;                    // [32 kk][256 col][4 kp] = 32768 floats (128 KB)
    float* ib = sm + KK * 256;         // [2 buf][8 rows][VPITCH]

    const float* xp = x_is_scratch ? g_h1 : x_in;

    const int tid = threadIdx.x;
    const int j   = tid >> 2;          // hidden unit 0..63
    const int rg  = tid & 3;           // row group -> rows 2rg, 2rg+1
    const int r0  = rg * 2;
    const int row_base = blockIdx.x * ROWS;

    // ---- stage weights: wq[kk*1024 + col*4 + kp], col = unit*4 + gate, k = kk*4+kp
    // v[k] = h[k] (k<64) or x[k-64]
    for (int idx = tid; idx < KK * 256; idx += NTHR) {
        int kp = idx & 3;
        int c  = (idx >> 2) & 255;
        int kk = idx >> 10;
        int k  = kk * 4 + kp;
        int ju = c >> 2, qu = c & 3;
        int g  = qu * 64 + ju;
        wq[idx] = (k < 64) ? w_hh[g * 64 + k] : w_ih[g * 64 + (k - 64)];
    }

    // ---- init buffer 0: h part = 0, x part = x[:, 0, :]
    {
        int r = tid & 7, u = tid >> 3;   // u 0..31
        ib[r * VPITCH + u]      = 0.0f;
        ib[r * VPITCH + u + 32] = 0.0f;
        ib[r * VPITCH + 64 + u] = xp[(size_t)(row_base + r) * TT * HH + u];
        ib[r * VPITCH + 96 + u] = xp[(size_t)(row_base + r) * TT * HH + 32 + u];
    }

    // per-thread gate biases (i,f,g,o of unit j)
    float bias[4];
    #pragma unroll
    for (int q = 0; q < 4; q++) bias[q] = b_ih[q * 64 + j] + b_hh[q * 64 + j];

    float c0 = 0.0f, c1 = 0.0f;        // cell state for rows r0, r0+1

    // x prefetch mapping: thread covers (row xr; dims xd, xd+32)
    const int xr = tid & 7, xd = tid >> 3;
    const float* xrow = xp + (size_t)(row_base + xr) * TT * HH + xd;

    __syncthreads();

    int pb = 0;
    for (int t = 0; t < TT; t++) {
        int tn = (t + 1 < TT) ? (t + 1) : t;
        float xa = xrow[(size_t)tn * HH];
        float xb = xrow[(size_t)tn * HH + 32];

        // acc[r][q]: fp32x2 packed over k parity; rows r in {0,1}, gates q 0..3
        unsigned long long acc[2][4];
        #pragma unroll
        for (int r = 0; r < 2; r++)
            #pragma unroll
            for (int q = 0; q < 4; q++) acc[r][q] = 0ull;

        const float* vb = ib + pb * (8 * VPITCH);
        const float* v0p = vb + r0 * VPITCH;
        const float* v1p = vb + (r0 + 1) * VPITCH;
        const float* wp  = wq + j * 16;   // 4 cols x 4 kp

        #pragma unroll 8
        for (int kk = 0; kk < 32; kk++) {
            ulonglong2 v0 = *reinterpret_cast<const ulonglong2*>(v0p + kk * 4);
            ulonglong2 v1 = *reinterpret_cast<const ulonglong2*>(v1p + kk * 4);
            const float* wc = wp + (size_t)kk * 1024;
            #pragma unroll
            for (int q = 0; q < 4; q++) {
                ulonglong2 w2 = *reinterpret_cast<const ulonglong2*>(wc + q * 4);
                fma2(acc[0][q], v0.x, w2.x);
                fma2(acc[0][q], v0.y, w2.y);
                fma2(acc[1][q], v1.x, w2.x);
                fma2(acc[1][q], v1.y, w2.y);
            }
        }

        // ---- finish dot products, activations, state update (both rows)
        float z[2][4];
        #pragma unroll
        for (int r = 0; r < 2; r++)
            #pragma unroll
            for (int q = 0; q < 4; q++) {
                float2 fr = unpack2(acc[r][q]);
                z[r][q] = (fr.x + fr.y) + bias[q];
            }

        float i0 = fsig(z[0][0]), f0 = fsig(z[0][1]), g0 = ftanhf(z[0][2]), o0 = fsig(z[0][3]);
        float i1 = fsig(z[1][0]), f1 = fsig(z[1][1]), g1 = ftanhf(z[1][2]), o1 = fsig(z[1][3]);

        c0 = f0 * c0 + i0 * g0;
        c1 = f1 * c1 + i1 * g1;
        float h0 = o0 * ftanhf(c0);
        float h1 = o1 * ftanhf(c1);

        // ---- write next-step inputs into the other buffer
        float* nb = ib + (pb ^ 1) * (8 * VPITCH);
        nb[r0 * VPITCH + j]       = h0;
        nb[(r0 + 1) * VPITCH + j] = h1;
        nb[xr * VPITCH + 64 + xd] = xa;
        nb[xr * VPITCH + 96 + xd] = xb;

        if (store_seq) {
            g_h1[((size_t)(row_base + r0) * TT + t) * HH + j]     = h0;
            g_h1[((size_t)(row_base + r0 + 1) * TT + t) * HH + j] = h1;
        }
        if (store_last && t == TT - 1) {
            g_hlast[(row_base + r0) * HH + j]     = h0;
            g_hlast[(row_base + r0 + 1) * HH + j] = h1;
        }

        __syncthreads();
        pb ^= 1;
    }
}

// out[b][o] = softplus(h_last[b] . fc_w[o] + fc_b[o]),  O=32
__global__ void fc_softplus(const float* __restrict__ fc_w,
                            const float* __restrict__ fc_b,
                            float* __restrict__ out)
{
    __shared__ float wsh[64 * 32];   // [k][o] transposed
    __shared__ float bsh[32];
    const int tid = threadIdx.x;     // 128 threads

    for (int idx = tid; idx < 64 * 32; idx += 128) {
        int k = idx >> 5, o = idx & 31;
        wsh[idx] = fc_w[o * 64 + k];
    }
    if (tid < 32) bsh[tid] = fc_b[tid];
    __syncthreads();

    int gid = blockIdx.x * 128 + tid;
    int b = gid >> 5, o = gid & 31;
    const float* hr = g_hlast + b * 64;

    float z = bsh[o];
    #pragma unroll
    for (int k = 0; k < 64; k++)
        z += hr[k] * wsh[k * 32 + o];

    float r = (z > 20.0f) ? z : log1pf(__expf(z));
    out[gid] = r;
}

extern "C" void kernel_launch(void* const* d_in, const int* in_sizes, int n_in,
                              void* d_out, int out_size)
{
    (void)in_sizes; (void)n_in; (void)out_size;
    const float* x    = (const float*)d_in[0];
    const float* wih0 = (const float*)d_in[1];
    const float* whh0 = (const float*)d_in[2];
    const float* bih0 = (const float*)d_in[3];
    const float* bhh0 = (const float*)d_in[4];
    const float* wih1 = (const float*)d_in[5];
    const float* whh1 = (const float*)d_in[6];
    const float* bih1 = (const float*)d_in[7];
    const float* bhh1 = (const float*)d_in[8];
    const float* fcw  = (const float*)d_in[9];
    const float* fcb  = (const float*)d_in[10];
    float* out = (float*)d_out;

    const size_t smem = (size_t)(KK * 256 + 2 * 8 * VPITCH) * sizeof(float); // 139,520 B
    cudaFuncSetAttribute(lstm_layer, cudaFuncAttributeMaxDynamicSharedMemorySize, (int)smem);

    // layer 0: reads x, stores full h1 sequence
    lstm_layer<<<BB / ROWS, NTHR, smem>>>(x, wih0, whh0, bih0, bhh0, 1, 0, 0);
    // layer 1: reads h1 scratch, stores only final h
    lstm_layer<<<BB / ROWS, NTHR, smem>>>(nullptr, wih1, whh1, bih1, bhh1, 0, 1, 1);
    // FC + softplus
    fc_softplus<<<(BB * 32) / 128, 128>>>(fcw, fcb, out);
}

// round 4
// speedup vs baseline: 1.3724x; 1.3724x over previous
#include <cuda_runtime.h>
#include <math.h>

#define BB   1024
#define TT   512
#define HH   64
#define KK   128
#define ROWS 8
#define NTHR 256
#define VPITCH 132          // words per input row in smem (conflict-free padding)
#define LOG2E 1.4426950408889634f

// Scratch (static __device__ arrays are the allowed scratch mechanism)
__device__ float g_h1[(size_t)BB * TT * HH];   // layer-0 hidden sequence [B][T][H]
__device__ float g_hlast[BB * HH];             // layer-1 final hidden state

__device__ __forceinline__ void fma2(unsigned long long &d,
                                     unsigned long long a, unsigned long long b) {
    asm("fma.rn.f32x2 %0, %1, %2, %0;" : "+l"(d) : "l"(a), "l"(b));
}
__device__ __forceinline__ float ex2f(float x) {
    float r; asm("ex2.approx.f32 %0, %1;" : "=f"(r) : "f"(x)); return r;
}
__device__ __forceinline__ float rcpf(float x) {
    float r; asm("rcp.approx.f32 %0, %1;" : "=f"(r) : "f"(x)); return r;
}
__device__ __forceinline__ float2 unpack2(unsigned long long v) {
    float2 f; asm("mov.b64 {%0, %1}, %2;" : "=f"(f.x), "=f"(f.y) : "l"(v)); return f;
}
__device__ __forceinline__ float fsig(float x) {      // sigmoid, ~1e-7 rel err
    return rcpf(1.0f + ex2f(-LOG2E * x));
}
__device__ __forceinline__ float ftanhf(float x) {    // tanh = 2*sig(2x)-1
    return fmaf(rcpf(1.0f + ex2f(-2.0f * LOG2E * x)), 2.0f, -1.0f);
}

// One LSTM layer, batch-first, PyTorch gate order (i,f,g,o).
// CTA = 8 batch rows, 256 threads = (unit j 0..63) x (row-group rg 0..3).
// Thread (j, rg) computes ALL FOUR gates of unit j for rows {2rg, 2rg+1};
// the c/h update is thread-local (no shuffles).
//
// Weight smem layout is GATE-MAJOR: wq[kk][g][kp] with g = q*64 + j.
// A warp's per-kk w-load for fixed q covers j=0..7 at 4-word stride =
// 32 contiguous words = all 32 banks (4-lane broadcast) -> 1 wavefront.
// (R3's unit-major layout was a 4-way bank conflict; this fixes it.)
__global__ void __launch_bounds__(NTHR, 1)
lstm_layer(const float* __restrict__ x_in,
           const float* __restrict__ w_ih, const float* __restrict__ w_hh,
           const float* __restrict__ b_ih, const float* __restrict__ b_hh,
           int store_seq, int store_last, int x_is_scratch)
{
    extern __shared__ float sm[];
    float* wq = sm;                    // [32 kk][256 g][4 kp] = 32768 floats (128 KB)
    float* ib = sm + KK * 256;         // [2 buf][8 rows][VPITCH]

    const float* xp = x_is_scratch ? g_h1 : x_in;

    const int tid = threadIdx.x;
    const int j   = tid >> 2;          // hidden unit 0..63
    const int rg  = tid & 3;           // row group -> rows 2rg, 2rg+1
    const int r0  = rg * 2;
    const int row_base = blockIdx.x * ROWS;

    // ---- stage weights: wq[kk*1024 + g*4 + kp], g = gate*64 + unit, k = kk*4+kp
    // v[k] = h[k] (k<64) or x[k-64]
    for (int idx = tid; idx < KK * 256; idx += NTHR) {
        int kp = idx & 3;
        int g  = (idx >> 2) & 255;     // gate-major row index == weight row
        int kk = idx >> 10;
        int k  = kk * 4 + kp;
        wq[idx] = (k < 64) ? w_hh[g * 64 + k] : w_ih[g * 64 + (k - 64)];
    }

    // ---- init buffer 0: h part = 0, x part = x[:, 0, :]
    {
        int r = tid & 7, u = tid >> 3;   // u 0..31
        ib[r * VPITCH + u]      = 0.0f;
        ib[r * VPITCH + u + 32] = 0.0f;
        ib[r * VPITCH + 64 + u] = xp[(size_t)(row_base + r) * TT * HH + u];
        ib[r * VPITCH + 96 + u] = xp[(size_t)(row_base + r) * TT * HH + 32 + u];
    }

    // per-thread gate biases (i,f,g,o of unit j)
    float bias[4];
    #pragma unroll
    for (int q = 0; q < 4; q++) bias[q] = b_ih[q * 64 + j] + b_hh[q * 64 + j];

    float c0 = 0.0f, c1 = 0.0f;        // cell state for rows r0, r0+1

    // x prefetch mapping: thread covers (row xr; dims xd, xd+32)
    const int xr = tid & 7, xd = tid >> 3;
    const float* xrow = xp + (size_t)(row_base + xr) * TT * HH + xd;

    __syncthreads();

    int pb = 0;
    for (int t = 0; t < TT; t++) {
        int tn = (t + 1 < TT) ? (t + 1) : t;
        float xa = xrow[(size_t)tn * HH];
        float xb = xrow[(size_t)tn * HH + 32];

        // acc[r][q]: fp32x2 packed over k parity; rows r in {0,1}, gates q 0..3
        unsigned long long acc[2][4];
        #pragma unroll
        for (int r = 0; r < 2; r++)
            #pragma unroll
            for (int q = 0; q < 4; q++) acc[r][q] = 0ull;

        const float* vb  = ib + pb * (8 * VPITCH);
        const float* v0p = vb + r0 * VPITCH;
        const float* v1p = vb + (r0 + 1) * VPITCH;
        const float* wp  = wq + j * 4;    // + q*256 + kk*1024

        #pragma unroll 8
        for (int kk = 0; kk < 32; kk++) {
            ulonglong2 v0 = *reinterpret_cast<const ulonglong2*>(v0p + kk * 4);
            ulonglong2 v1 = *reinterpret_cast<const ulonglong2*>(v1p + kk * 4);
            const float* wc = wp + (size_t)kk * 1024;
            #pragma unroll
            for (int q = 0; q < 4; q++) {
                ulonglong2 w2 = *reinterpret_cast<const ulonglong2*>(wc + q * 256);
                fma2(acc[0][q], v0.x, w2.x);
                fma2(acc[0][q], v0.y, w2.y);
                fma2(acc[1][q], v1.x, w2.x);
                fma2(acc[1][q], v1.y, w2.y);
            }
        }

        // ---- finish dot products, activations, state update (both rows)
        float z[2][4];
        #pragma unroll
        for (int r = 0; r < 2; r++)
            #pragma unroll
            for (int q = 0; q < 4; q++) {
                float2 fr = unpack2(acc[r][q]);
                z[r][q] = (fr.x + fr.y) + bias[q];
            }

        float i0 = fsig(z[0][0]), f0 = fsig(z[0][1]), g0 = ftanhf(z[0][2]), o0 = fsig(z[0][3]);
        float i1 = fsig(z[1][0]), f1 = fsig(z[1][1]), g1 = ftanhf(z[1][2]), o1 = fsig(z[1][3]);

        c0 = f0 * c0 + i0 * g0;
        c1 = f1 * c1 + i1 * g1;
        float h0 = o0 * ftanhf(c0);
        float h1 = o1 * ftanhf(c1);

        // ---- write next-step inputs into the other buffer
        float* nb = ib + (pb ^ 1) * (8 * VPITCH);
        nb[r0 * VPITCH + j]       = h0;
        nb[(r0 + 1) * VPITCH + j] = h1;
        nb[xr * VPITCH + 64 + xd] = xa;
        nb[xr * VPITCH + 96 + xd] = xb;

        if (store_seq) {
            g_h1[((size_t)(row_base + r0) * TT + t) * HH + j]     = h0;
            g_h1[((size_t)(row_base + r0 + 1) * TT + t) * HH + j] = h1;
        }
        if (store_last && t == TT - 1) {
            g_hlast[(row_base + r0) * HH + j]     = h0;
            g_hlast[(row_base + r0 + 1) * HH + j] = h1;
        }

        __syncthreads();
        pb ^= 1;
    }
}

// out[b][o] = softplus(h_last[b] . fc_w[o] + fc_b[o]),  O=32
__global__ void fc_softplus(const float* __restrict__ fc_w,
                            const float* __restrict__ fc_b,
                            float* __restrict__ out)
{
    __shared__ float wsh[64 * 32];   // [k][o] transposed
    __shared__ float bsh[32];
    const int tid = threadIdx.x;     // 128 threads

    for (int idx = tid; idx < 64 * 32; idx += 128) {
        int k = idx >> 5, o = idx & 31;
        wsh[idx] = fc_w[o * 64 + k];
    }
    if (tid < 32) bsh[tid] = fc_b[tid];
    __syncthreads();

    int gid = blockIdx.x * 128 + tid;
    int b = gid >> 5, o = gid & 31;
    const float* hr = g_hlast + b * 64;

    float z = bsh[o];
    #pragma unroll
    for (int k = 0; k < 64; k++)
        z += hr[k] * wsh[k * 32 + o];

    float r = (z > 20.0f) ? z : log1pf(__expf(z));
    out[gid] = r;
}

extern "C" void kernel_launch(void* const* d_in, const int* in_sizes, int n_in,
                              void* d_out, int out_size)
{
    (void)in_sizes; (void)n_in; (void)out_size;
    const float* x    = (const float*)d_in[0];
    const float* wih0 = (const float*)d_in[1];
    const float* whh0 = (const float*)d_in[2];
    const float* bih0 = (const float*)d_in[3];
    const float* bhh0 = (const float*)d_in[4];
    const float* wih1 = (const float*)d_in[5];
    const float* whh1 = (const float*)d_in[6];
    const float* bih1 = (const float*)d_in[7];
    const float* bhh1 = (const float*)d_in[8];
    const float* fcw  = (const float*)d_in[9];
    const float* fcb  = (const float*)d_in[10];
    float* out = (float*)d_out;

    const size_t smem = (size_t)(KK * 256 + 2 * 8 * VPITCH) * sizeof(float); // 139,520 B
    cudaFuncSetAttribute(lstm_layer, cudaFuncAttributeMaxDynamicSharedMemorySize, (int)smem);

    // layer 0: reads x, stores full h1 sequence
    lstm_layer<<<BB / ROWS, NTHR, smem>>>(x, wih0, whh0, bih0, bhh0, 1, 0, 0);
    // layer 1: reads h1 scratch, stores only final h
    lstm_layer<<<BB / ROWS, NTHR, smem>>>(nullptr, wih1, whh1, bih1, bhh1, 0, 1, 1);
    // FC + softplus
    fc_softplus<<<(BB * 32) / 128, 128>>>(fcw, fcb, out);
}